// round 15
// baseline (speedup 1.0000x reference)
#include <cuda_runtime.h>
#include <stdint.h>

typedef unsigned long long u64;

// ---- packed fp32x2 primitives (SASS FFMA2 path, 2x fp32 throughput) ----
__device__ __forceinline__ u64 fma2(u64 a, u64 b, u64 c) {
    u64 d; asm("fma.rn.f32x2 %0, %1, %2, %3;" : "=l"(d) : "l"(a), "l"(b), "l"(c)); return d;
}
__device__ __forceinline__ u64 mul2(u64 a, u64 b) {
    u64 d; asm("mul.rn.f32x2 %0, %1, %2;" : "=l"(d) : "l"(a), "l"(b)); return d;
}
__device__ __forceinline__ u64 pack2(float lo, float hi) {
    u64 d; asm("mov.b64 %0, {%1, %2};" : "=l"(d) : "f"(lo), "f"(hi)); return d;
}
__device__ __forceinline__ void unpack2(u64 v, float& lo, float& hi) {
    asm("mov.b64 {%0, %1}, %2;" : "=f"(lo), "=f"(hi) : "l"(v));
}

// leaky(x) = max(x, 0.01x)  (exact elementwise for slope<1)
__device__ __forceinline__ u64 leaky2(u64 x) {
    const u64 SL = 0x3C23D70A3C23D70AULL;  // (0.01f, 0.01f)
    u64 s = mul2(x, SL);
    float xl, xh, sl, sh;
    unpack2(x, xl, xh); unpack2(s, sl, sh);
    return pack2(fmaxf(xl, sl), fmaxf(xh, sh));
}

struct Params { const float* p[20]; };  // [0..4]=ws_logs [5..9]=bs_logs [10..14]=ws_b [15..19]=bs_b

// All constants in ONE symbol (single memcpy into the bank).
struct ConstPack {
    ulonglong2 W[2][5][32];   // [(w2i,w2i),(w2i+1,w2i+1)] granules
    ulonglong2 B[2][5][4];    // bias dup-pairs
};
__constant__ ConstPack CP;
__device__ ConstPack GP_scratch;

__global__ void pack_params_kernel(Params P)
{
    int tid = threadIdx.x;
    for (int idx = tid; idx < 320; idx += blockDim.x) {
        int m = idx / 160, r = idx % 160, l = r / 32, k = r % 32;
        int j = k / 4, i2 = k % 4;
        const float* Wp = P.p[m * 10 + l];
        float w0 = Wp[j * 8 + i2 * 2], w1 = Wp[j * 8 + i2 * 2 + 1];
        GP_scratch.W[m][l][k] = make_ulonglong2(pack2(w0, w0), pack2(w1, w1));
    }
    for (int idx = tid; idx < 40; idx += blockDim.x) {
        int m = idx / 20, r = idx % 20, l = r / 4, k = r % 4;
        const float* Bp = P.p[m * 10 + 5 + l];
        float b0 = Bp[2 * k], b1 = Bp[2 * k + 1];
        GP_scratch.B[m][l][k] = make_ulonglong2(pack2(b0, b0), pack2(b1, b1));
    }
}

// One 8->8 layer on TWO packed row-pairs; weights via CONSTANT memory
// (compile-time offsets, template M, L).
template <int M, int L>
__device__ __forceinline__ void layerC(
    const u64* in0, const u64* in1, u64* out0, u64* out1, bool act)
{
#pragma unroll
    for (int j2 = 0; j2 < 4; j2++) {
        ulonglong2 bias = CP.B[M][L][j2];
        u64 a0 = bias.x, a1 = bias.x;           // row j = 2*j2
        u64 c0 = bias.y, c1 = bias.y;           // row j = 2*j2+1
#pragma unroll
        for (int i2 = 0; i2 < 4; i2++) {
            ulonglong2 wa = CP.W[M][L][(2 * j2)     * 4 + i2];
            ulonglong2 wc = CP.W[M][L][(2 * j2 + 1) * 4 + i2];
            a0 = fma2(wa.x, in0[2 * i2],     a0);
            a1 = fma2(wa.x, in1[2 * i2],     a1);
            a0 = fma2(wa.y, in0[2 * i2 + 1], a0);
            a1 = fma2(wa.y, in1[2 * i2 + 1], a1);
            c0 = fma2(wc.x, in0[2 * i2],     c0);
            c1 = fma2(wc.x, in1[2 * i2],     c1);
            c0 = fma2(wc.y, in0[2 * i2 + 1], c0);
            c1 = fma2(wc.y, in1[2 * i2 + 1], c1);
        }
        out0[2 * j2]     = act ? leaky2(a0) : a0;
        out1[2 * j2]     = act ? leaky2(a1) : a1;
        out0[2 * j2 + 1] = act ? leaky2(c0) : c0;
        out1[2 * j2 + 1] = act ? leaky2(c1) : c1;
    }
}

template <int IOW>
__device__ __forceinline__ float4 ld4(const float* p) {
    if (IOW == 4) return *(const float4*)p;
    else if (IOW == 2) { float2 u = *(const float2*)p, v = *(const float2*)(p + 2);
                         return make_float4(u.x, u.y, v.x, v.y); }
    else return make_float4(p[0], p[1], p[2], p[3]);
}
template <int IOW>
__device__ __forceinline__ void st4(float* p, float4 v) {
    if (IOW == 4) *(float4*)p = v;
    else if (IOW == 2) { *(float2*)p = make_float2(v.x, v.y);
                         *(float2*)(p + 2) = make_float2(v.z, v.w); }
    else { p[0] = v.x; p[1] = v.y; p[2] = v.z; p[3] = v.w; }
}

// Load + pack the LEFT halves of one thread's 4 rows into (rowA,rowB) pairs.
template <int IOW>
__device__ __forceinline__ void load_zl(const float* __restrict__ z,
                                        const int* rA, u64 zl[2][8])
{
#pragma unroll
    for (int p = 0; p < 2; p++) {
        const float* pa = z + (long long)rA[p] * 16;
        const float* pb = z + (long long)(rA[p] + 32) * 16;
        float4 a0 = ld4<IOW>(pa), a1 = ld4<IOW>(pa + 4);
        float4 b0 = ld4<IOW>(pb), b1 = ld4<IOW>(pb + 4);
        zl[p][0] = pack2(a0.x, b0.x); zl[p][1] = pack2(a0.y, b0.y);
        zl[p][2] = pack2(a0.z, b0.z); zl[p][3] = pack2(a0.w, b0.w);
        zl[p][4] = pack2(a1.x, b1.x); zl[p][5] = pack2(a1.y, b1.y);
        zl[p][6] = pack2(a1.z, b1.z); zl[p][7] = pack2(a1.w, b1.w);
    }
}

// IOW: I/O width in floats per memory op (4 = float4, 2 = float2, 1 = scalar)
template <int IOW>
__global__ __launch_bounds__(128, 5)
void affine_coupling_kernel(const float* __restrict__ z, float* __restrict__ out,
                            int batch)
{
    // Per-thread private stash for exp(log_s): dense [slot][tid] layout,
    // conflict-free 16B accesses, NO __syncthreads needed (own slot only).
    __shared__ ulonglong2 ELS[8][128];   // 16 KB/block

    const int tid = threadIdx.x;
    const int lane = tid & 31;
    const int warp = tid >> 5;
    long long warpBase = ((long long)blockIdx.x * 4 + warp) * 128;
    if (warpBase >= batch) return;  // batch % 128 == 0 -> active warps are full

    int rA[2];
    rA[0] = (int)warpBase + lane;
    rA[1] = rA[0] + 64;

    u64 s[2][8], t[2][8];

    // ---- pass 1: load zl, store left passthrough, run log_s chain ----
    {
        u64 zl[2][8];
        load_zl<IOW>(z, rA, zl);
#pragma unroll
        for (int p = 0; p < 2; p++) {
            // left-half passthrough (raw copy of what we just loaded)
            float* oa = out + (long long)rA[p] * 16;
            float* ob = out + (long long)(rA[p] + 32) * 16;
            float lo, hi;
            float4 w0, w1;
            unpack2(zl[p][0], w0.x, lo); unpack2(zl[p][1], w0.y, hi);
            unpack2(zl[p][2], w0.z, lo); unpack2(zl[p][3], w0.w, hi);
            unpack2(zl[p][4], w1.x, lo); unpack2(zl[p][5], w1.y, hi);
            unpack2(zl[p][6], w1.z, lo); unpack2(zl[p][7], w1.w, hi);
            st4<IOW>(oa, w0); st4<IOW>(oa + 4, w1);
            float4 v0, v1; float d;
            unpack2(zl[p][0], d, v0.x); unpack2(zl[p][1], d, v0.y);
            unpack2(zl[p][2], d, v0.z); unpack2(zl[p][3], d, v0.w);
            unpack2(zl[p][4], d, v1.x); unpack2(zl[p][5], d, v1.y);
            unpack2(zl[p][6], d, v1.z); unpack2(zl[p][7], d, v1.w);
            st4<IOW>(ob, v0); st4<IOW>(ob + 4, v1);
        }
        layerC<0, 0>(zl[0], zl[1], s[0], s[1], true);   // zl dies here
    }
    layerC<0, 1>(s[0], s[1], t[0], t[1], true);
    layerC<0, 2>(t[0], t[1], s[0], s[1], true);
    layerC<0, 3>(s[0], s[1], t[0], t[1], true);
    layerC<0, 4>(t[0], t[1], s[0], s[1], false);   // s = log_s

    // s = exp(log_s), packed; stash to private smem slot.
#pragma unroll
    for (int p = 0; p < 2; p++)
#pragma unroll
        for (int k2 = 0; k2 < 4; k2++) {
            float lA0, lB0, lA1, lB1;
            unpack2(s[p][2 * k2],     lA0, lB0);
            unpack2(s[p][2 * k2 + 1], lA1, lB1);
            ELS[p * 4 + k2][tid] = make_ulonglong2(
                pack2(__expf(lA0), __expf(lB0)),
                pack2(__expf(lA1), __expf(lB1)));
        }

    // ---- pass 2: reload zl (L2 hit), run b chain ----
    {
        u64 zl[2][8];
        load_zl<IOW>(z, rA, zl);
        layerC<1, 0>(zl[0], zl[1], s[0], s[1], true);   // zl dies here
    }
    layerC<1, 1>(s[0], s[1], t[0], t[1], true);
    layerC<1, 2>(t[0], t[1], s[0], s[1], true);
    layerC<1, 3>(s[0], s[1], t[0], t[1], true);
    layerC<1, 4>(t[0], t[1], s[0], s[1], false);   // s = b

    // ---- epilogue per pair: yr = exp(log_s) * zr + b ----
#pragma unroll
    for (int p = 0; p < 2; p++) {
        const float* pa = z + (long long)rA[p] * 16 + 8;
        const float* pb = z + (long long)(rA[p] + 32) * 16 + 8;
        float4 a2 = ld4<IOW>(pa), a3 = ld4<IOW>(pa + 4);
        float4 b2 = ld4<IOW>(pb), b3 = ld4<IOW>(pb + 4);

        u64 zr[8];
        zr[0] = pack2(a2.x, b2.x); zr[1] = pack2(a2.y, b2.y);
        zr[2] = pack2(a2.z, b2.z); zr[3] = pack2(a2.w, b2.w);
        zr[4] = pack2(a3.x, b3.x); zr[5] = pack2(a3.y, b3.y);
        zr[6] = pack2(a3.z, b3.z); zr[7] = pack2(a3.w, b3.w);

        float yA[8], yB[8];
#pragma unroll
        for (int k2 = 0; k2 < 4; k2++) {
            ulonglong2 e = ELS[p * 4 + k2][tid];
            u64 y0 = fma2(e.x, zr[2 * k2],     s[p][2 * k2]);
            u64 y1 = fma2(e.y, zr[2 * k2 + 1], s[p][2 * k2 + 1]);
            unpack2(y0, yA[2 * k2],     yB[2 * k2]);
            unpack2(y1, yA[2 * k2 + 1], yB[2 * k2 + 1]);
        }
        float* oa = out + (long long)rA[p] * 16 + 8;
        float* ob = out + (long long)(rA[p] + 32) * 16 + 8;
        st4<IOW>(oa,     make_float4(yA[0], yA[1], yA[2], yA[3]));
        st4<IOW>(oa + 4, make_float4(yA[4], yA[5], yA[6], yA[7]));
        st4<IOW>(ob,     make_float4(yB[0], yB[1], yB[2], yB[3]));
        st4<IOW>(ob + 4, make_float4(yB[4], yB[5], yB[6], yB[7]));
    }
}

extern "C" void kernel_launch(void* const* d_in, const int* in_sizes, int n_in,
                              void* d_out, int out_size)
{
    // ---- locate z: the (unique) huge input ----
    int zi = 0;
    for (int i = 0; i < n_in; i++) {
        if (in_sizes[i] > in_sizes[zi]) zi = i;
    }
    const float* z = (const float*)d_in[zi];
    long long batchLL = (long long)in_sizes[zi] / 16;
    int batch = (int)batchLL;
    float* out = (float*)d_out;

    // ---- build the 20 layer-parameter pointers, layout-adaptively ----
    Params P;
    if (n_in >= 21) {
        int k = 0;
        for (int i = 0; i < n_in && k < 20; i++) {
            if (i == zi) continue;
            P.p[k++] = (const float*)d_in[i];
        }
    } else {
        int wslot = 0, bslot = 0;  // 0 -> logs, 1 -> b
        for (int i = 0; i < n_in; i++) {
            if (i == zi) continue;
            const float* base = (const float*)d_in[i];
            int sz = in_sizes[i];
            if (sz == 320) {            // stacked weights (5,8,8)
                int m = (wslot++ == 0) ? 0 : 1;
                for (int l = 0; l < 5; l++) P.p[m * 10 + l] = base + 64 * l;
            } else if (sz == 40) {      // stacked biases (5,8)
                int m = (bslot++ == 0) ? 0 : 1;
                for (int l = 0; l < 5; l++) P.p[m * 10 + 5 + l] = base + 8 * l;
            }
        }
    }

    // prologue: pack dup-pairs into device scratch, then ONE D2D copy into the
    // constant bank (device address resolved explicitly).
    pack_params_kernel<<<1, 384>>>(P);
    void* gp_dev = nullptr;
    cudaGetSymbolAddress(&gp_dev, GP_scratch);
    cudaMemcpyToSymbolAsync(CP, gp_dev, sizeof(ConstPack), 0, cudaMemcpyDeviceToDevice, 0);

    int rowsPerBlock = 512;                // 128 threads * 4 rows
    int grid = (int)((batchLL + rowsPerBlock - 1) / rowsPerBlock);

    uintptr_t mis = (uintptr_t)z | (uintptr_t)out;
    if ((mis & 15) == 0) {
        affine_coupling_kernel<4><<<grid, 128>>>(z, out, batch);
    } else if ((mis & 7) == 0) {
        affine_coupling_kernel<2><<<grid, 128>>>(z, out, batch);
    } else {
        affine_coupling_kernel<1><<<grid, 128>>>(z, out, batch);
    }
}

// round 16
// speedup vs baseline: 1.0357x; 1.0357x over previous
#include <cuda_runtime.h>
#include <stdint.h>

typedef unsigned long long u64;

// ---- packed fp32x2 primitives (SASS FFMA2 path, 2x fp32 throughput) ----
__device__ __forceinline__ u64 fma2(u64 a, u64 b, u64 c) {
    u64 d; asm("fma.rn.f32x2 %0, %1, %2, %3;" : "=l"(d) : "l"(a), "l"(b), "l"(c)); return d;
}
__device__ __forceinline__ u64 mul2(u64 a, u64 b) {
    u64 d; asm("mul.rn.f32x2 %0, %1, %2;" : "=l"(d) : "l"(a), "l"(b)); return d;
}
__device__ __forceinline__ u64 pack2(float lo, float hi) {
    u64 d; asm("mov.b64 %0, {%1, %2};" : "=l"(d) : "f"(lo), "f"(hi)); return d;
}
__device__ __forceinline__ void unpack2(u64 v, float& lo, float& hi) {
    asm("mov.b64 {%0, %1}, %2;" : "=f"(lo), "=f"(hi) : "l"(v));
}
__device__ __forceinline__ float ex2f(float x) {
    float r; asm("ex2.approx.f32 %0, %1;" : "=f"(r) : "f"(x)); return r;
}

// leaky(x) = max(x, 0.01x)  (exact elementwise for slope<1)
__device__ __forceinline__ u64 leaky2(u64 x) {
    const u64 SL = 0x3C23D70A3C23D70AULL;  // (0.01f, 0.01f)
    u64 s = mul2(x, SL);
    float xl, xh, sl, sh;
    unpack2(x, xl, xh); unpack2(s, sl, sh);
    return pack2(fmaxf(xl, sl), fmaxf(xh, sh));
}

struct Params { const float* p[20]; };  // [0..4]=ws_logs [5..9]=bs_logs [10..14]=ws_b [15..19]=bs_b

// Weights in CONSTANT memory: compile-time addresses -> const port, off L1tex.
__constant__ ulonglong2 CW[2][5][32];   // [(w2i,w2i),(w2i+1,w2i+1)] granules
__constant__ ulonglong2 CB[2][5][4];    // bias dup-pairs

// Device scratch the pack kernel writes; D2D-memcpy'd into CW/CB.
__device__ ulonglong2 GW_scratch[2][5][32];
__device__ ulonglong2 GB_scratch[2][5][4];

__global__ void pack_params_kernel(Params P)
{
    int tid = threadIdx.x;
    for (int idx = tid; idx < 320; idx += blockDim.x) {
        int m = idx / 160, r = idx % 160, l = r / 32, k = r % 32;
        int j = k / 4, i2 = k % 4;
        const float* Wp = P.p[m * 10 + l];
        float w0 = Wp[j * 8 + i2 * 2], w1 = Wp[j * 8 + i2 * 2 + 1];
        GW_scratch[m][l][k] = make_ulonglong2(pack2(w0, w0), pack2(w1, w1));
    }
    for (int idx = tid; idx < 40; idx += blockDim.x) {
        int m = idx / 20, r = idx % 20, l = r / 4, k = r % 4;
        const float* Bp = P.p[m * 10 + 5 + l];
        float b0 = Bp[2 * k], b1 = Bp[2 * k + 1];
        GB_scratch[m][l][k] = make_ulonglong2(pack2(b0, b0), pack2(b1, b1));
    }
}

// One 8->8 layer on TWO packed row-pairs; weights via constant memory with
// compile-time offsets (template M, L).
template <int M, int L>
__device__ __forceinline__ void layerC(
    const u64* in0, const u64* in1, u64* out0, u64* out1, bool act)
{
#pragma unroll
    for (int j2 = 0; j2 < 4; j2++) {
        ulonglong2 bias = CB[M][L][j2];
        u64 a0 = bias.x, a1 = bias.x;           // row j = 2*j2
        u64 c0 = bias.y, c1 = bias.y;           // row j = 2*j2+1
#pragma unroll
        for (int i2 = 0; i2 < 4; i2++) {
            ulonglong2 wa = CW[M][L][(2 * j2)     * 4 + i2];
            ulonglong2 wc = CW[M][L][(2 * j2 + 1) * 4 + i2];
            a0 = fma2(wa.x, in0[2 * i2],     a0);
            a1 = fma2(wa.x, in1[2 * i2],     a1);
            a0 = fma2(wa.y, in0[2 * i2 + 1], a0);
            a1 = fma2(wa.y, in1[2 * i2 + 1], a1);
            c0 = fma2(wc.x, in0[2 * i2],     c0);
            c1 = fma2(wc.x, in1[2 * i2],     c1);
            c0 = fma2(wc.y, in0[2 * i2 + 1], c0);
            c1 = fma2(wc.y, in1[2 * i2 + 1], c1);
        }
        out0[2 * j2]     = act ? leaky2(a0) : a0;
        out1[2 * j2]     = act ? leaky2(a1) : a1;
        out0[2 * j2 + 1] = act ? leaky2(c0) : c0;
        out1[2 * j2 + 1] = act ? leaky2(c1) : c1;
    }
}

template <int IOW>
__device__ __forceinline__ float4 ld4(const float* p) {
    if (IOW == 4) return *(const float4*)p;
    else if (IOW == 2) { float2 u = *(const float2*)p, v = *(const float2*)(p + 2);
                         return make_float4(u.x, u.y, v.x, v.y); }
    else return make_float4(p[0], p[1], p[2], p[3]);
}
template <int IOW>
__device__ __forceinline__ void st4(float* p, float4 v) {
    if (IOW == 4) *(float4*)p = v;
    else if (IOW == 2) { *(float2*)p = make_float2(v.x, v.y);
                         *(float2*)(p + 2) = make_float2(v.z, v.w); }
    else { p[0] = v.x; p[1] = v.y; p[2] = v.z; p[3] = v.w; }
}

// Byte-offset layout per thread (row = 64 bytes):
//   pair p base      : + p*4096           (64 rows)
//   rowB             : + 2048             (32 rows)
//   right half (zr)  : + 32
//   second float4    : + 16

// IOW: I/O width in floats per memory op (4 = float4, 2 = float2, 1 = scalar)
template <int IOW>
__global__ __launch_bounds__(128, 4)
void affine_coupling_kernel(const float* __restrict__ z, float* __restrict__ out,
                            int batch)
{
    const int tid = threadIdx.x;
    const int lane = tid & 31;
    const int warp = tid >> 5;
    long long warpBase = ((long long)blockIdx.x * 4 + warp) * 128;
    if (warpBase >= batch) return;  // batch % 128 == 0 -> active warps are full

    const int rA0 = (int)warpBase + lane;
    const char* zc = (const char*)z + (long long)rA0 * 64;  // row = 64B
    char* oc = (char*)out + (long long)rA0 * 64;

    u64 zl[2][8];
#pragma unroll
    for (int p = 0; p < 2; p++) {
        const char* zp = zc + p * 4096;
        char* op = oc + p * 4096;
        // front halves only (zr deferred to epilogue to cut live registers)
        float4 a0 = ld4<IOW>((const float*)(zp));
        float4 a1 = ld4<IOW>((const float*)(zp + 16));
        float4 b0 = ld4<IOW>((const float*)(zp + 2048));
        float4 b1 = ld4<IOW>((const float*)(zp + 2064));

        // left-half passthrough: store immediately
        st4<IOW>((float*)(op),        a0);
        st4<IOW>((float*)(op + 16),   a1);
        st4<IOW>((float*)(op + 2048), b0);
        st4<IOW>((float*)(op + 2064), b1);

        zl[p][0] = pack2(a0.x, b0.x); zl[p][1] = pack2(a0.y, b0.y);
        zl[p][2] = pack2(a0.z, b0.z); zl[p][3] = pack2(a0.w, b0.w);
        zl[p][4] = pack2(a1.x, b1.x); zl[p][5] = pack2(a1.y, b1.y);
        zl[p][6] = pack2(a1.z, b1.z); zl[p][7] = pack2(a1.w, b1.w);
    }

    u64 s[2][8], t[2][8];

    // ---- log_s chain (m=0); zl stays alive for the b chain ----
    layerC<0, 0>(zl[0], zl[1], s[0], s[1], true);
    layerC<0, 1>(s[0], s[1], t[0], t[1], true);
    layerC<0, 2>(t[0], t[1], s[0], s[1], true);
    layerC<0, 3>(s[0], s[1], t[0], t[1], true);
    u64 ls[2][8];
    layerC<0, 4>(t[0], t[1], ls[0], ls[1], false);

    // els = exp(log_s), packed: mul2 by log2(e) then ex2 on halves.
    const u64 L2E2 = 0x3FB8AA3B3FB8AA3BULL;  // (log2e, log2e)
    u64 els[2][8];
#pragma unroll
    for (int p = 0; p < 2; p++)
#pragma unroll
        for (int j = 0; j < 8; j++) {
            u64 m = mul2(ls[p][j], L2E2);
            float mA, mB; unpack2(m, mA, mB);
            els[p][j] = pack2(ex2f(mA), ex2f(mB));
        }

    // ---- b chain (m=1); zl dies after layer 0 ----
    layerC<1, 0>(zl[0], zl[1], s[0], s[1], true);
    layerC<1, 1>(s[0], s[1], t[0], t[1], true);
    layerC<1, 2>(t[0], t[1], s[0], s[1], true);
    layerC<1, 3>(s[0], s[1], t[0], t[1], true);
    u64 bv[2][8];
    layerC<1, 4>(t[0], t[1], bv[0], bv[1], false);

    // ---- epilogue: load zr now, yr = exp(log_s) * zr + b ----
#pragma unroll
    for (int p = 0; p < 2; p++) {
        const char* zp = zc + p * 4096 + 32;   // right half
        char* op = oc + p * 4096 + 32;
        float4 a2 = ld4<IOW>((const float*)(zp));
        float4 a3 = ld4<IOW>((const float*)(zp + 16));
        float4 b2 = ld4<IOW>((const float*)(zp + 2048));
        float4 b3 = ld4<IOW>((const float*)(zp + 2064));

        u64 zr[8];
        zr[0] = pack2(a2.x, b2.x); zr[1] = pack2(a2.y, b2.y);
        zr[2] = pack2(a2.z, b2.z); zr[3] = pack2(a2.w, b2.w);
        zr[4] = pack2(a3.x, b3.x); zr[5] = pack2(a3.y, b3.y);
        zr[6] = pack2(a3.z, b3.z); zr[7] = pack2(a3.w, b3.w);

        float yA[8], yB[8];
#pragma unroll
        for (int j = 0; j < 8; j++) {
            u64 y = fma2(els[p][j], zr[j], bv[p][j]);
            unpack2(y, yA[j], yB[j]);
        }
        st4<IOW>((float*)(op),        make_float4(yA[0], yA[1], yA[2], yA[3]));
        st4<IOW>((float*)(op + 16),   make_float4(yA[4], yA[5], yA[6], yA[7]));
        st4<IOW>((float*)(op + 2048), make_float4(yB[0], yB[1], yB[2], yB[3]));
        st4<IOW>((float*)(op + 2064), make_float4(yB[4], yB[5], yB[6], yB[7]));
    }
}

extern "C" void kernel_launch(void* const* d_in, const int* in_sizes, int n_in,
                              void* d_out, int out_size)
{
    // ---- locate z: the (unique) huge input ----
    int zi = 0;
    for (int i = 0; i < n_in; i++) {
        if (in_sizes[i] > in_sizes[zi]) zi = i;
    }
    const float* z = (const float*)d_in[zi];
    long long batchLL = (long long)in_sizes[zi] / 16;
    int batch = (int)batchLL;
    float* out = (float*)d_out;

    // ---- build the 20 layer-parameter pointers, layout-adaptively ----
    Params P;
    if (n_in >= 21) {
        int k = 0;
        for (int i = 0; i < n_in && k < 20; i++) {
            if (i == zi) continue;
            P.p[k++] = (const float*)d_in[i];
        }
    } else {
        int wslot = 0, bslot = 0;  // 0 -> logs, 1 -> b
        for (int i = 0; i < n_in; i++) {
            if (i == zi) continue;
            const float* base = (const float*)d_in[i];
            int sz = in_sizes[i];
            if (sz == 320) {            // stacked weights (5,8,8)
                int m = (wslot++ == 0) ? 0 : 1;
                for (int l = 0; l < 5; l++) P.p[m * 10 + l] = base + 64 * l;
            } else if (sz == 40) {      // stacked biases (5,8)
                int m = (bslot++ == 0) ? 0 : 1;
                for (int l = 0; l < 5; l++) P.p[m * 10 + 5 + l] = base + 8 * l;
            }
        }
    }

    // prologue: pack dup-pairs into device scratch, then D2D-copy into the
    // constant bank (device address resolved explicitly).
    pack_params_kernel<<<1, 128>>>(P);
    void *gw_dev = nullptr, *gb_dev = nullptr;
    cudaGetSymbolAddress(&gw_dev, GW_scratch);
    cudaGetSymbolAddress(&gb_dev, GB_scratch);
    cudaMemcpyToSymbolAsync(CW, gw_dev, sizeof(CW), 0, cudaMemcpyDeviceToDevice, 0);
    cudaMemcpyToSymbolAsync(CB, gb_dev, sizeof(CB), 0, cudaMemcpyDeviceToDevice, 0);

    int rowsPerBlock = 512;                // 128 threads * 4 rows
    int grid = (int)((batchLL + rowsPerBlock - 1) / rowsPerBlock);

    uintptr_t mis = (uintptr_t)z | (uintptr_t)out;
    if ((mis & 15) == 0) {
        affine_coupling_kernel<4><<<grid, 128>>>(z, out, batch);
    } else if ((mis & 7) == 0) {
        affine_coupling_kernel<2><<<grid, 128>>>(z, out, batch);
    } else {
        affine_coupling_kernel<1><<<grid, 128>>>(z, out, batch);
    }
}

// round 17
// speedup vs baseline: 1.1249x; 1.0861x over previous
#include <cuda_runtime.h>
#include <stdint.h>

typedef unsigned long long u64;

// ---- packed fp32x2 primitives (SASS FFMA2 path, 2x fp32 throughput) ----
__device__ __forceinline__ u64 fma2(u64 a, u64 b, u64 c) {
    u64 d; asm("fma.rn.f32x2 %0, %1, %2, %3;" : "=l"(d) : "l"(a), "l"(b), "l"(c)); return d;
}
__device__ __forceinline__ u64 mul2(u64 a, u64 b) {
    u64 d; asm("mul.rn.f32x2 %0, %1, %2;" : "=l"(d) : "l"(a), "l"(b)); return d;
}
__device__ __forceinline__ u64 pack2(float lo, float hi) {
    u64 d; asm("mov.b64 %0, {%1, %2};" : "=l"(d) : "f"(lo), "f"(hi)); return d;
}
__device__ __forceinline__ void unpack2(u64 v, float& lo, float& hi) {
    asm("mov.b64 {%0, %1}, %2;" : "=f"(lo), "=f"(hi) : "l"(v));
}
__device__ __forceinline__ float ex2f(float x) {
    float r; asm("ex2.approx.f32 %0, %1;" : "=f"(r) : "f"(x)); return r;
}

// leaky(x) = max(x, 0.01x)  (exact elementwise for slope<1)
__device__ __forceinline__ u64 leaky2(u64 x) {
    const u64 SL = 0x3C23D70A3C23D70AULL;  // (0.01f, 0.01f)
    u64 s = mul2(x, SL);
    float xl, xh, sl, sh;
    unpack2(x, xl, xh); unpack2(s, sl, sh);
    return pack2(fmaxf(xl, sl), fmaxf(xh, sh));
}

struct Params { const float* p[20]; };  // [0..4]=ws_logs [5..9]=bs_logs [10..14]=ws_b [15..19]=bs_b

// Weights in CONSTANT memory: compile-time addresses -> const port, off L1tex.
__constant__ ulonglong2 CW[2][5][32];   // [(w2i,w2i),(w2i+1,w2i+1)] granules
__constant__ ulonglong2 CB[2][5][4];    // bias dup-pairs

// Device scratch the pack kernel writes; D2D-memcpy'd into CW/CB.
__device__ ulonglong2 GW_scratch[2][5][32];
__device__ ulonglong2 GB_scratch[2][5][4];

__global__ void pack_params_kernel(Params P)
{
    int tid = threadIdx.x;
    for (int idx = tid; idx < 320; idx += blockDim.x) {
        int m = idx / 160, r = idx % 160, l = r / 32, k = r % 32;
        int j = k / 4, i2 = k % 4;
        const float* Wp = P.p[m * 10 + l];
        float w0 = Wp[j * 8 + i2 * 2], w1 = Wp[j * 8 + i2 * 2 + 1];
        GW_scratch[m][l][k] = make_ulonglong2(pack2(w0, w0), pack2(w1, w1));
    }
    for (int idx = tid; idx < 40; idx += blockDim.x) {
        int m = idx / 20, r = idx % 20, l = r / 4, k = r % 4;
        const float* Bp = P.p[m * 10 + 5 + l];
        float b0 = Bp[2 * k], b1 = Bp[2 * k + 1];
        GB_scratch[m][l][k] = make_ulonglong2(pack2(b0, b0), pack2(b1, b1));
    }
}

// One 8->8 layer on TWO packed row-pairs; weights via constant memory with
// compile-time offsets (template M, L).
template <int M, int L>
__device__ __forceinline__ void layerC(
    const u64* in0, const u64* in1, u64* out0, u64* out1, bool act)
{
#pragma unroll
    for (int j2 = 0; j2 < 4; j2++) {
        ulonglong2 bias = CB[M][L][j2];
        u64 a0 = bias.x, a1 = bias.x;           // row j = 2*j2
        u64 c0 = bias.y, c1 = bias.y;           // row j = 2*j2+1
#pragma unroll
        for (int i2 = 0; i2 < 4; i2++) {
            ulonglong2 wa = CW[M][L][(2 * j2)     * 4 + i2];
            ulonglong2 wc = CW[M][L][(2 * j2 + 1) * 4 + i2];
            a0 = fma2(wa.x, in0[2 * i2],     a0);
            a1 = fma2(wa.x, in1[2 * i2],     a1);
            a0 = fma2(wa.y, in0[2 * i2 + 1], a0);
            a1 = fma2(wa.y, in1[2 * i2 + 1], a1);
            c0 = fma2(wc.x, in0[2 * i2],     c0);
            c1 = fma2(wc.x, in1[2 * i2],     c1);
            c0 = fma2(wc.y, in0[2 * i2 + 1], c0);
            c1 = fma2(wc.y, in1[2 * i2 + 1], c1);
        }
        out0[2 * j2]     = act ? leaky2(a0) : a0;
        out1[2 * j2]     = act ? leaky2(a1) : a1;
        out0[2 * j2 + 1] = act ? leaky2(c0) : c0;
        out1[2 * j2 + 1] = act ? leaky2(c1) : c1;
    }
}

template <int IOW>
__device__ __forceinline__ float4 ld4(const float* p) {
    if (IOW == 4) return *(const float4*)p;
    else if (IOW == 2) { float2 u = *(const float2*)p, v = *(const float2*)(p + 2);
                         return make_float4(u.x, u.y, v.x, v.y); }
    else return make_float4(p[0], p[1], p[2], p[3]);
}
template <int IOW>
__device__ __forceinline__ void st4(float* p, float4 v) {
    if (IOW == 4) *(float4*)p = v;
    else if (IOW == 2) { *(float2*)p = make_float2(v.x, v.y);
                         *(float2*)(p + 2) = make_float2(v.z, v.w); }
    else { p[0] = v.x; p[1] = v.y; p[2] = v.z; p[3] = v.w; }
}

// IOW: I/O width in floats per memory op (4 = float4, 2 = float2, 1 = scalar)
template <int IOW>
__global__ __launch_bounds__(128, 4)
void affine_coupling_kernel(const float* __restrict__ z, float* __restrict__ out,
                            int batch)
{
    const int tid = threadIdx.x;
    const int lane = tid & 31;
    const int warp = tid >> 5;
    long long warpBase = ((long long)blockIdx.x * 4 + warp) * 128;
    if (warpBase >= batch) return;  // batch % 128 == 0 -> active warps are full

    // Each thread: 2 pairs = 4 rows. Pair p = (warpBase + 64p + lane, +32).
    int rA[2];
    u64 zl[2][8];
#pragma unroll
    for (int p = 0; p < 2; p++) {
        rA[p] = (int)warpBase + p * 64 + lane;
        const float* pa = z + (long long)rA[p] * 16;
        const float* pb = z + (long long)(rA[p] + 32) * 16;
        // front halves only (zr deferred to epilogue to cut live registers)
        float4 a0 = ld4<IOW>(pa), a1 = ld4<IOW>(pa + 4);
        float4 b0 = ld4<IOW>(pb), b1 = ld4<IOW>(pb + 4);

        // left-half passthrough: store immediately
        float* oa = out + (long long)rA[p] * 16;
        float* ob = out + (long long)(rA[p] + 32) * 16;
        st4<IOW>(oa, a0);     st4<IOW>(oa + 4, a1);
        st4<IOW>(ob, b0);     st4<IOW>(ob + 4, b1);

        zl[p][0] = pack2(a0.x, b0.x); zl[p][1] = pack2(a0.y, b0.y);
        zl[p][2] = pack2(a0.z, b0.z); zl[p][3] = pack2(a0.w, b0.w);
        zl[p][4] = pack2(a1.x, b1.x); zl[p][5] = pack2(a1.y, b1.y);
        zl[p][6] = pack2(a1.z, b1.z); zl[p][7] = pack2(a1.w, b1.w);
    }

    u64 s[2][8], t[2][8];

    // ---- log_s chain (m=0); zl stays alive for the b chain ----
    layerC<0, 0>(zl[0], zl[1], s[0], s[1], true);
    layerC<0, 1>(s[0], s[1], t[0], t[1], true);
    layerC<0, 2>(t[0], t[1], s[0], s[1], true);
    layerC<0, 3>(s[0], s[1], t[0], t[1], true);
    u64 ls[2][8];
    layerC<0, 4>(t[0], t[1], ls[0], ls[1], false);

    // els = exp(log_s), packed: one mul2 by log2(e), then ex2 on the halves.
    const u64 L2E2 = 0x3FB8AA3B3FB8AA3BULL;  // (log2e, log2e)
    u64 els[2][8];
#pragma unroll
    for (int p = 0; p < 2; p++)
#pragma unroll
        for (int j = 0; j < 8; j++) {
            u64 m = mul2(ls[p][j], L2E2);
            float mA, mB; unpack2(m, mA, mB);
            els[p][j] = pack2(ex2f(mA), ex2f(mB));
        }

    // ---- b chain (m=1); zl dies after layer 0 ----
    layerC<1, 0>(zl[0], zl[1], s[0], s[1], true);
    layerC<1, 1>(s[0], s[1], t[0], t[1], true);
    layerC<1, 2>(t[0], t[1], s[0], s[1], true);
    layerC<1, 3>(s[0], s[1], t[0], t[1], true);
    u64 bv[2][8];
    layerC<1, 4>(t[0], t[1], bv[0], bv[1], false);

    // ---- epilogue: load zr now, yr = exp(log_s) * zr + b ----
#pragma unroll
    for (int p = 0; p < 2; p++) {
        const float* pa = z + (long long)rA[p] * 16 + 8;
        const float* pb = z + (long long)(rA[p] + 32) * 16 + 8;
        float4 a2 = ld4<IOW>(pa), a3 = ld4<IOW>(pa + 4);
        float4 b2 = ld4<IOW>(pb), b3 = ld4<IOW>(pb + 4);

        u64 zr[8];
        zr[0] = pack2(a2.x, b2.x); zr[1] = pack2(a2.y, b2.y);
        zr[2] = pack2(a2.z, b2.z); zr[3] = pack2(a2.w, b2.w);
        zr[4] = pack2(a3.x, b3.x); zr[5] = pack2(a3.y, b3.y);
        zr[6] = pack2(a3.z, b3.z); zr[7] = pack2(a3.w, b3.w);

        float yA[8], yB[8];
#pragma unroll
        for (int j = 0; j < 8; j++) {
            u64 y = fma2(els[p][j], zr[j], bv[p][j]);
            unpack2(y, yA[j], yB[j]);
        }
        float* oa = out + (long long)rA[p] * 16 + 8;
        float* ob = out + (long long)(rA[p] + 32) * 16 + 8;
        st4<IOW>(oa,     make_float4(yA[0], yA[1], yA[2], yA[3]));
        st4<IOW>(oa + 4, make_float4(yA[4], yA[5], yA[6], yA[7]));
        st4<IOW>(ob,     make_float4(yB[0], yB[1], yB[2], yB[3]));
        st4<IOW>(ob + 4, make_float4(yB[4], yB[5], yB[6], yB[7]));
    }
}

extern "C" void kernel_launch(void* const* d_in, const int* in_sizes, int n_in,
                              void* d_out, int out_size)
{
    // ---- locate z: the (unique) huge input ----
    int zi = 0;
    for (int i = 0; i < n_in; i++) {
        if (in_sizes[i] > in_sizes[zi]) zi = i;
    }
    const float* z = (const float*)d_in[zi];
    long long batchLL = (long long)in_sizes[zi] / 16;
    int batch = (int)batchLL;
    float* out = (float*)d_out;

    // ---- build the 20 layer-parameter pointers, layout-adaptively ----
    Params P;
    if (n_in >= 21) {
        int k = 0;
        for (int i = 0; i < n_in && k < 20; i++) {
            if (i == zi) continue;
            P.p[k++] = (const float*)d_in[i];
        }
    } else {
        int wslot = 0, bslot = 0;  // 0 -> logs, 1 -> b
        for (int i = 0; i < n_in; i++) {
            if (i == zi) continue;
            const float* base = (const float*)d_in[i];
            int sz = in_sizes[i];
            if (sz == 320) {            // stacked weights (5,8,8)
                int m = (wslot++ == 0) ? 0 : 1;
                for (int l = 0; l < 5; l++) P.p[m * 10 + l] = base + 64 * l;
            } else if (sz == 40) {      // stacked biases (5,8)
                int m = (bslot++ == 0) ? 0 : 1;
                for (int l = 0; l < 5; l++) P.p[m * 10 + 5 + l] = base + 8 * l;
            }
        }
    }

    // prologue: pack dup-pairs into device scratch, then D2D-copy into the
    // constant bank (device address resolved explicitly).
    pack_params_kernel<<<1, 128>>>(P);
    void *gw_dev = nullptr, *gb_dev = nullptr;
    cudaGetSymbolAddress(&gw_dev, GW_scratch);
    cudaGetSymbolAddress(&gb_dev, GB_scratch);
    cudaMemcpyToSymbolAsync(CW, gw_dev, sizeof(CW), 0, cudaMemcpyDeviceToDevice, 0);
    cudaMemcpyToSymbolAsync(CB, gb_dev, sizeof(CB), 0, cudaMemcpyDeviceToDevice, 0);

    int rowsPerBlock = 512;                // 128 threads * 4 rows
    int grid = (int)((batchLL + rowsPerBlock - 1) / rowsPerBlock);

    uintptr_t mis = (uintptr_t)z | (uintptr_t)out;
    if ((mis & 15) == 0) {
        affine_coupling_kernel<4><<<grid, 128>>>(z, out, batch);
    } else if ((mis & 7) == 0) {
        affine_coupling_kernel<2><<<grid, 128>>>(z, out, batch);
    } else {
        affine_coupling_kernel<1><<<grid, 128>>>(z, out, batch);
    }
}